// round 2
// baseline (speedup 1.0000x reference)
#include <cuda_runtime.h>
#include <cstdint>

#define BB 8
#define SS 2048
#define DD 64
#define NSAMP 50

// Scratch (no cudaMalloc allowed): positional embedding + scalar type embedding
__device__ float g_pe[BB * SS * DD];   // 4 MB
__device__ float g_emb[BB * SS];       // 64 KB

// ---------------------------------------------------------------------------
// Kernel 1: biased positional embedding + type embedding scalar
// pe[b,s,k]    = sin(s*div[k] + t*Wt[k]),  pe[b,s,32+k] = cos(...)
// emb[b,s]     = type_table[type] * 8 * (type != 0)
// ---------------------------------------------------------------------------
__global__ void pe_kernel(const int* __restrict__ etype,
                          const float* __restrict__ etime,
                          const float* __restrict__ Wt_pos,
                          const float* __restrict__ type_table) {
    int idx = blockIdx.x * blockDim.x + threadIdx.x;
    if (idx >= BB * SS * 32) return;
    int k = idx & 31;
    int s = (idx >> 5) & (SS - 1);
    int b = idx >> 16;            // 32 * 2048 = 65536
    int bs = b * SS + s;
    float t = etime[bs];
    // div_term[k] = exp(2k * (-ln(10000)/64))
    float div = expf((float)(2 * k) * -0.14391156831212787f);
    float a = (float)s * div + t * Wt_pos[k];
    g_pe[bs * DD + k]      = sinf(a);
    g_pe[bs * DD + 32 + k] = cosf(a);
    if (k == 0) {
        int ty = etype[bs];
        float e = (ty == 0) ? 0.0f : type_table[ty] * 8.0f;  // sqrt(64)=8
        g_emb[bs] = e;
    }
}

// ---------------------------------------------------------------------------
// Kernel 2: hidden = causal(scores) @ pe, fused LayerNorm.
// Block: (b, i-tile of 64 rows), 256 threads.
// Thread (ig=tid>>3 in 0..31, dg=tid&7): micro-tile 2 i-rows x 8 d-cols.
// j processed in tiles of 32: pe tile staged in smem, scores tile computed
// cooperatively into padded smem, then register-blocked FMA.
// ---------------------------------------------------------------------------
__global__ __launch_bounds__(256) void hidden_kernel(
    const float* __restrict__ etime,
    const float* __restrict__ gamma,
    const float* __restrict__ beta,
    float* __restrict__ hidden_out) {
    __shared__ float pe_s[32 * 64];     // 8 KB
    __shared__ float sc_s[64 * 33];     // padded: bank-conflict-free
    __shared__ float ti_s[64];
    __shared__ float ei_s[64];

    const int b  = blockIdx.y;
    const int it = 31 - blockIdx.x;     // biggest blocks first
    const int tid = threadIdx.x;
    const int dg = tid & 7;
    const int ig = tid >> 3;            // 0..31

    if (tid < 64) {
        ti_s[tid] = etime[b * SS + it * 64 + tid];
        ei_s[tid] = g_emb[b * SS + it * 64 + tid];
    }
    const float4 gm0 = ((const float4*)gamma)[dg * 2];
    const float4 gm1 = ((const float4*)gamma)[dg * 2 + 1];
    const float4 bt0 = ((const float4*)beta)[dg * 2];
    const float4 bt1 = ((const float4*)beta)[dg * 2 + 1];

    float acc[2][8];
#pragma unroll
    for (int k = 0; k < 2; k++)
#pragma unroll
        for (int m = 0; m < 8; m++) acc[k][m] = 0.0f;

    const int ntiles = 2 * it + 2;
    const float4* gpe4 = (const float4*)g_pe;
    const int si  = tid & 63;          // score row
    const int sj0 = (tid >> 6) * 8;    // score jj group (8 per thread)

    __syncthreads();

    for (int jt = 0; jt < ntiles; jt++) {
        // stage pe tile: 32 rows x 64 = 512 float4
        const int base4 = (b * SS + jt * 32) * 16;
        ((float4*)pe_s)[tid]       = gpe4[base4 + tid];
        ((float4*)pe_s)[tid + 256] = gpe4[base4 + tid + 256];

        // compute scores tile
        const float tii = ti_s[si];
        const float eii = ei_s[si];
        const int iglob = it * 64 + si;
#pragma unroll
        for (int m = 0; m < 8; m++) {
            const int jj = sj0 + m;
            const int jglob = jt * 32 + jj;
            const float tj = __ldg(&etime[b * SS + jglob]);
            const float ej = g_emb[b * SS + jglob];
            const float td = tii - tj;
            const float base = 1.0f / (1.0f + 0.5f * td * td);
            const float gate = 1.0f / (1.0f + expf(fabsf(eii - ej)));
            sc_s[si * 33 + jj] = (jglob <= iglob) ? base * gate : 0.0f;
        }
        __syncthreads();

        const float4* p4 = (const float4*)pe_s;
#pragma unroll 4
        for (int jj = 0; jj < 32; jj++) {
            const float4 p0 = p4[jj * 16 + dg * 2];
            const float4 p1 = p4[jj * 16 + dg * 2 + 1];
#pragma unroll
            for (int k = 0; k < 2; k++) {
                const float sv = sc_s[(ig * 2 + k) * 33 + jj];
                acc[k][0] += sv * p0.x; acc[k][1] += sv * p0.y;
                acc[k][2] += sv * p0.z; acc[k][3] += sv * p0.w;
                acc[k][4] += sv * p1.x; acc[k][5] += sv * p1.y;
                acc[k][6] += sv * p1.z; acc[k][7] += sv * p1.w;
            }
        }
        __syncthreads();
    }

    // fused LayerNorm over D=64 (8 lanes x 8 values per row)
#pragma unroll
    for (int k = 0; k < 2; k++) {
        float sum = 0.0f, sq = 0.0f;
#pragma unroll
        for (int m = 0; m < 8; m++) { sum += acc[k][m]; sq += acc[k][m] * acc[k][m]; }
#pragma unroll
        for (int o = 1; o < 8; o <<= 1) {
            sum += __shfl_xor_sync(0xffffffffu, sum, o);
            sq  += __shfl_xor_sync(0xffffffffu, sq,  o);
        }
        const float mu  = sum * (1.0f / 64.0f);
        const float var = sq * (1.0f / 64.0f) - mu * mu;
        const float inv = rsqrtf(var + 1e-6f);
        const int row = it * 64 + ig * 2 + k;
        float* outp = hidden_out + ((size_t)(b * SS + row)) * 64 + dg * 8;
        float4 o0, o1;
        o0.x = (acc[k][0] - mu) * inv * gm0.x + bt0.x;
        o0.y = (acc[k][1] - mu) * inv * gm0.y + bt0.y;
        o0.z = (acc[k][2] - mu) * inv * gm0.z + bt0.z;
        o0.w = (acc[k][3] - mu) * inv * gm0.w + bt0.w;
        o1.x = (acc[k][4] - mu) * inv * gm1.x + bt1.x;
        o1.y = (acc[k][5] - mu) * inv * gm1.y + bt1.y;
        o1.z = (acc[k][6] - mu) * inv * gm1.z + bt1.z;
        o1.w = (acc[k][7] - mu) * inv * gm1.w + bt1.w;
        ((float4*)outp)[0] = o0;
        ((float4*)outp)[1] = o1;
    }
}

// ---------------------------------------------------------------------------
// Kernel 3: GAN decoder.
// Block per (b,s), 128 threads = 2 warp-pairs; pair p handles samples p,p+2,...
// Each thread register-caches one full W_noise row (64 floats). Noise rows
// double-buffered through smem: one 64-thread named barrier per sample.
// ---------------------------------------------------------------------------
__device__ __forceinline__ float softplusf(float x) {
    return fmaxf(x, 0.0f) + log1pf(expf(-fabsf(x)));
}

__global__ __launch_bounds__(128) void decoder_kernel(
    const float* __restrict__ noise,
    const float* __restrict__ W_in,
    const float* __restrict__ W_noise,
    const float* __restrict__ W_event,
    const float* __restrict__ hidden,
    float* __restrict__ mean_out) {
    __shared__ float  h_s[64];
    __shared__ float  proj_s[64];
    __shared__ float  wev_s[64];
    __shared__ float4 nbuf[2][2][16];   // [pair][buf][16 float4]
    __shared__ float  psum[2][2][2];    // [pair][parity][sub]
    __shared__ float  pacc[2];

    const int s = blockIdx.x, b = blockIdx.y;
    const int bs = b * SS + s;
    const int tid  = threadIdx.x;
    const int lane = tid & 31;
    const int warp = tid >> 5;
    const int pair = warp >> 1;
    const int sub  = warp & 1;
    const int e    = sub * 32 + lane;

    if (tid < 64) h_s[tid] = hidden[(size_t)bs * 64 + tid];
    else          wev_s[tid - 64] = W_event[tid - 64];
    __syncthreads();

    // proj[e] = W_in[e,:] . hidden
    if (tid < 64) {
        const float4* wi = (const float4*)W_in + tid * 16;
        const float4* h4 = (const float4*)h_s;
        float p = 0.0f;
#pragma unroll
        for (int d4 = 0; d4 < 16; d4++) {
            const float4 w = __ldg(&wi[d4]);
            const float4 h = h4[d4];
            p += w.x * h.x + w.y * h.y + w.z * h.z + w.w * h.w;
        }
        proj_s[tid] = p;
    }
    // register-cache this thread's W_noise row
    float4 wr[16];
    {
        const float4* wn = (const float4*)W_noise + e * 16;
#pragma unroll
        for (int i = 0; i < 16; i++) wr[i] = __ldg(&wn[i]);
    }
    __syncthreads();
    const float wev_e = wev_s[e];
    const float pj    = proj_s[e];

    const float* nrow = noise + (size_t)bs * NSAMP * 64;
    // stage first sample (n = pair) into buf 0
    {
        const float4* src = (const float4*)(nrow + pair * 64);
        if (e < 16) nbuf[pair][0][e] = src[e];
    }

    float acc = 0.0f;
    for (int idx = 0; idx < 25; idx++) {
        const int buf = idx & 1;
        asm volatile("bar.sync %0, 64;" :: "r"(pair + 1) : "memory");
        if (idx > 0 && sub == 0 && lane == 0) {
            const int pp = (idx - 1) & 1;
            acc += softplusf(psum[pair][pp][0] + psum[pair][pp][1]);
        }
        float z = pj;
#pragma unroll
        for (int d4 = 0; d4 < 16; d4++) {
            const float4 nv = nbuf[pair][buf][d4];
            const float4 w  = wr[d4];
            z += nv.x * w.x + nv.y * w.y + nv.z * w.z + nv.w * w.w;
        }
        // prefetch next sample into the other buffer
        if (idx + 1 < 25) {
            const int n = pair + 2 * (idx + 1);
            const float4* src = (const float4*)(nrow + n * 64);
            if (e < 16) nbuf[pair][buf ^ 1][e] = src[e];
        }
        float g = fmaxf(z, 0.0f) * wev_e;
#pragma unroll
        for (int o = 16; o > 0; o >>= 1) g += __shfl_xor_sync(0xffffffffu, g, o);
        if (lane == 0) psum[pair][idx & 1][sub] = g;
    }
    asm volatile("bar.sync %0, 64;" :: "r"(pair + 1) : "memory");
    if (sub == 0 && lane == 0) {
        acc += softplusf(psum[pair][0][0] + psum[pair][0][1]);  // idx=24 parity 0
        pacc[pair] = acc;
    }
    __syncthreads();
    if (tid == 0) mean_out[bs] = (pacc[0] + pacc[1]) * (1.0f / NSAMP);
}

// ---------------------------------------------------------------------------
extern "C" void kernel_launch(void* const* d_in, const int* in_sizes, int n_in,
                              void* d_out, int out_size) {
    const int*   event_type = (const int*)d_in[0];
    const float* event_time = (const float*)d_in[1];
    // d_in[2] = arrival_times (unused by forward)
    const float* noise      = (const float*)d_in[3];
    const float* Wt_pos     = (const float*)d_in[4];
    const float* type_table = (const float*)d_in[5];
    const float* gamma      = (const float*)d_in[6];
    const float* beta       = (const float*)d_in[7];
    const float* W_in       = (const float*)d_in[8];
    const float* W_noise    = (const float*)d_in[9];
    const float* W_event    = (const float*)d_in[10];

    float* out        = (float*)d_out;
    float* mean_out   = out;               // [B,S]
    float* hidden_out = out + BB * SS;     // [B,S,D]

    pe_kernel<<<(BB * SS * 32 + 255) / 256, 256>>>(event_type, event_time,
                                                   Wt_pos, type_table);
    hidden_kernel<<<dim3(32, BB), 256>>>(event_time, gamma, beta, hidden_out);
    decoder_kernel<<<dim3(SS, BB), 128>>>(noise, W_in, W_noise, W_event,
                                          hidden_out, mean_out);
}

// round 3
// speedup vs baseline: 1.0760x; 1.0760x over previous
#include <cuda_runtime.h>
#include <cstdint>

#define BB 8
#define SS 2048
#define DD 64
#define NSAMP 50

typedef unsigned long long u64;

__device__ float g_pe[BB * SS * DD];   // 4 MB scratch
__device__ float g_emb[BB * SS];       // 64 KB scratch

// ---- packed f32x2 helpers (Blackwell) -------------------------------------
__device__ __forceinline__ u64 pack2(float lo, float hi) {
    u64 r; asm("mov.b64 %0,{%1,%2};" : "=l"(r) : "f"(lo), "f"(hi)); return r;
}
__device__ __forceinline__ void fma2(u64& a, u64 x, u64 y) {
    asm("fma.rn.f32x2 %0,%1,%2,%0;" : "+l"(a) : "l"(x), "l"(y));
}
__device__ __forceinline__ u64 add2(u64 x, u64 y) {
    u64 r; asm("add.rn.f32x2 %0,%1,%2;" : "=l"(r) : "l"(x), "l"(y)); return r;
}
__device__ __forceinline__ float2 unpack2(u64 a) {
    float2 v; asm("mov.b64 {%0,%1},%2;" : "=f"(v.x), "=f"(v.y) : "l"(a)); return v;
}
__device__ __forceinline__ float softplusf(float x) {
    return fmaxf(x, 0.0f) + log1pf(expf(-fabsf(x)));
}

// ---------------------------------------------------------------------------
// Kernel 1: biased positional embedding + type embedding scalar
// ---------------------------------------------------------------------------
__global__ void pe_kernel(const int* __restrict__ etype,
                          const float* __restrict__ etime,
                          const float* __restrict__ Wt_pos,
                          const float* __restrict__ type_table) {
    int idx = blockIdx.x * blockDim.x + threadIdx.x;
    if (idx >= BB * SS * 32) return;
    int k = idx & 31;
    int s = (idx >> 5) & (SS - 1);
    int b = idx >> 16;
    int bs = b * SS + s;
    float t = etime[bs];
    float div = expf((float)(2 * k) * -0.14391156831212787f);
    float a = (float)s * div + t * Wt_pos[k];
    g_pe[bs * DD + k]      = sinf(a);
    g_pe[bs * DD + 32 + k] = cosf(a);
    if (k == 0) {
        int ty = etype[bs];
        g_emb[bs] = (ty == 0) ? 0.0f : type_table[ty] * 8.0f;
    }
}

// ---------------------------------------------------------------------------
// Kernel 2: hidden = causal(scores) @ pe, fused LayerNorm.
// 32-row i-tiles, 512 blocks (heavy-first), 128 threads.
// Thread (ig=tid>>3, dg=tid&7): 2 rows x 8 d-cols, packed f32x2 FMAs.
// ---------------------------------------------------------------------------
__global__ __launch_bounds__(128) void hidden_kernel(
    const float* __restrict__ etime,
    const float* __restrict__ gamma,
    const float* __restrict__ beta,
    float* __restrict__ hidden_out) {
    __shared__ __align__(16) float pe_s[32 * 64];   // 8 KB
    __shared__ float sc_s[32 * 33];                 // padded
    __shared__ float ti_s[32], ei_s[32], tj_s[32], ej_s[32];

    const int b   = blockIdx.y;
    const int it  = 63 - blockIdx.x;   // heavy tiles first
    const int tid = threadIdx.x;
    const int dg  = tid & 7;
    const int ig  = tid >> 3;          // 0..15 -> rows 2ig, 2ig+1
    const int si  = tid & 31;          // score row
    const int sjg = tid >> 5;          // score jj group (8 each)

    if (tid < 32) {
        ti_s[tid] = etime[b * SS + it * 32 + tid];
        ei_s[tid] = g_emb[b * SS + it * 32 + tid];
    }
    const float4 gm0 = ((const float4*)gamma)[dg * 2];
    const float4 gm1 = ((const float4*)gamma)[dg * 2 + 1];
    const float4 bt0 = ((const float4*)beta)[dg * 2];
    const float4 bt1 = ((const float4*)beta)[dg * 2 + 1];

    u64 acc2[2][4];
#pragma unroll
    for (int k = 0; k < 2; k++)
#pragma unroll
        for (int m = 0; m < 4; m++) acc2[k][m] = 0ull;

    const int ntiles = it + 1;
    const float4* gpe4 = (const float4*)g_pe;
    __syncthreads();

    for (int jt = 0; jt < ntiles; jt++) {
        // stage pe tile (32 rows x 64 f = 512 float4) + tj/ej
        const int base4 = (b * SS + jt * 32) * 16;
#pragma unroll
        for (int r = 0; r < 4; r++)
            ((float4*)pe_s)[tid + 128 * r] = gpe4[base4 + tid + 128 * r];
        if (tid < 32) {
            tj_s[tid] = etime[b * SS + jt * 32 + tid];
            ej_s[tid] = g_emb[b * SS + jt * 32 + tid];
        }
        __syncthreads();

        // scores: 32x32, 8 per thread
        {
            const float tii = ti_s[si];
            const float eii = ei_s[si];
            const int iglob = it * 32 + si;
#pragma unroll
            for (int m = 0; m < 8; m++) {
                const int jj = sjg * 8 + m;
                const int jglob = jt * 32 + jj;
                const float td = tii - tj_s[jj];
                const float base = 1.0f / (1.0f + 0.5f * td * td);
                const float gate = 1.0f / (1.0f + expf(fabsf(eii - ej_s[jj])));
                sc_s[si * 33 + jj] = (jglob <= iglob) ? base * gate : 0.0f;
            }
        }
        __syncthreads();

        // packed FMA loop
#pragma unroll 4
        for (int jj = 0; jj < 32; jj++) {
            const ulonglong2* pr =
                (const ulonglong2*)(pe_s + jj * 64 + dg * 8);
            const ulonglong2 pa = pr[0];
            const ulonglong2 pb = pr[1];
            const float sv0 = sc_s[(2 * ig) * 33 + jj];
            const float sv1 = sc_s[(2 * ig + 1) * 33 + jj];
            const u64 s0 = pack2(sv0, sv0);
            const u64 s1 = pack2(sv1, sv1);
            fma2(acc2[0][0], s0, pa.x); fma2(acc2[0][1], s0, pa.y);
            fma2(acc2[0][2], s0, pb.x); fma2(acc2[0][3], s0, pb.y);
            fma2(acc2[1][0], s1, pa.x); fma2(acc2[1][1], s1, pa.y);
            fma2(acc2[1][2], s1, pb.x); fma2(acc2[1][3], s1, pb.y);
        }
        __syncthreads();
    }

    // fused LayerNorm (8-lane groups share a row)
#pragma unroll
    for (int k = 0; k < 2; k++) {
        float f[8];
#pragma unroll
        for (int m = 0; m < 4; m++) {
            float2 v = unpack2(acc2[k][m]);
            f[2 * m] = v.x; f[2 * m + 1] = v.y;
        }
        float sum = 0.0f, sq = 0.0f;
#pragma unroll
        for (int m = 0; m < 8; m++) { sum += f[m]; sq += f[m] * f[m]; }
#pragma unroll
        for (int o = 1; o < 8; o <<= 1) {
            sum += __shfl_xor_sync(0xffffffffu, sum, o);
            sq  += __shfl_xor_sync(0xffffffffu, sq,  o);
        }
        const float mu  = sum * (1.0f / 64.0f);
        const float var = sq * (1.0f / 64.0f) - mu * mu;
        const float inv = rsqrtf(var + 1e-6f);
        const int row = it * 32 + 2 * ig + k;
        float* outp = hidden_out + ((size_t)(b * SS + row)) * 64 + dg * 8;
        float4 o0, o1;
        o0.x = (f[0] - mu) * inv * gm0.x + bt0.x;
        o0.y = (f[1] - mu) * inv * gm0.y + bt0.y;
        o0.z = (f[2] - mu) * inv * gm0.z + bt0.z;
        o0.w = (f[3] - mu) * inv * gm0.w + bt0.w;
        o1.x = (f[4] - mu) * inv * gm1.x + bt1.x;
        o1.y = (f[5] - mu) * inv * gm1.y + bt1.y;
        o1.z = (f[6] - mu) * inv * gm1.z + bt1.z;
        o1.w = (f[7] - mu) * inv * gm1.w + bt1.w;
        ((float4*)outp)[0] = o0;
        ((float4*)outp)[1] = o1;
    }
}

// ---------------------------------------------------------------------------
// Kernel 3: GAN decoder. 64 threads per (b,s); thread = output unit e.
// W_noise row register-cached as 32 packed f32x2; noise rows read via
// uniform LDG.128 (L1 broadcast). No barriers/shuffles in the sample loop:
// per-sample relu(z)*w_event parked in padded smem, reduced once at the end.
// ---------------------------------------------------------------------------
__global__ __launch_bounds__(64) void decoder_kernel(
    const float* __restrict__ noise,
    const float* __restrict__ W_in,
    const float* __restrict__ W_noise,
    const float* __restrict__ W_event,
    const float* __restrict__ hidden,
    float* __restrict__ mean_out) {
    __shared__ float h_s[64];
    __shared__ float wstage[64][66];    // pad-66: conflict-light row reads
    __shared__ float gbuf[NSAMP][65];   // pad-65: conflict-free col reduce
    __shared__ float wred[2];

    const int s = blockIdx.x, b = blockIdx.y;
    const int bs = b * SS + s;
    const int e = threadIdx.x;

    h_s[e] = hidden[(size_t)bs * 64 + e];
    // stage W_in coalesced
    for (int idx = e; idx < 4096; idx += 64)
        wstage[idx >> 6][idx & 63] = W_in[idx];
    __syncthreads();

    // proj[e] = W_in[e,:] . hidden   (one-time)
    float pj = 0.0f;
#pragma unroll 16
    for (int d = 0; d < 64; d++) pj += wstage[e][d] * h_s[d];
    __syncthreads();

    // stage W_noise coalesced, then register-cache row e as 32 f32x2
    for (int idx = e; idx < 4096; idx += 64)
        wstage[idx >> 6][idx & 63] = W_noise[idx];
    __syncthreads();
    u64 wr[32];
#pragma unroll
    for (int j = 0; j < 32; j++) {
        const float2 v = *(const float2*)&wstage[e][2 * j];
        wr[j] = pack2(v.x, v.y);
    }
    const float wev = W_event[e];

    const ulonglong2* np =
        (const ulonglong2*)(noise + (size_t)bs * NSAMP * 64);

    for (int n = 0; n < NSAMP; n++) {
        const ulonglong2* row = np + n * 16;
        u64 acc[8];
#pragma unroll
        for (int m = 0; m < 8; m++) acc[m] = 0ull;
#pragma unroll
        for (int i = 0; i < 16; i++) {
            const ulonglong2 nv = row[i];
            fma2(acc[(2 * i) & 7],     nv.x, wr[2 * i]);
            fma2(acc[(2 * i + 1) & 7], nv.y, wr[2 * i + 1]);
        }
        u64 a0 = add2(add2(acc[0], acc[4]), add2(acc[2], acc[6]));
        u64 a1 = add2(add2(acc[1], acc[5]), add2(acc[3], acc[7]));
        float2 v = unpack2(add2(a0, a1));
        const float z = pj + v.x + v.y;
        gbuf[n][e] = fmaxf(z, 0.0f) * wev;
    }
    __syncthreads();

    // reduce: thread n sums over e, softplus, then block-sum
    float t = 0.0f;
    if (e < NSAMP) {
        float ssum = 0.0f;
#pragma unroll 16
        for (int d = 0; d < 64; d++) ssum += gbuf[e][d];
        t = softplusf(ssum);
    }
#pragma unroll
    for (int o = 16; o > 0; o >>= 1) t += __shfl_xor_sync(0xffffffffu, t, o);
    if ((e & 31) == 0) wred[e >> 5] = t;
    __syncthreads();
    if (e == 0) mean_out[bs] = (wred[0] + wred[1]) * (1.0f / NSAMP);
}

// ---------------------------------------------------------------------------
extern "C" void kernel_launch(void* const* d_in, const int* in_sizes, int n_in,
                              void* d_out, int out_size) {
    const int*   event_type = (const int*)d_in[0];
    const float* event_time = (const float*)d_in[1];
    const float* noise      = (const float*)d_in[3];
    const float* Wt_pos     = (const float*)d_in[4];
    const float* type_table = (const float*)d_in[5];
    const float* gamma      = (const float*)d_in[6];
    const float* beta       = (const float*)d_in[7];
    const float* W_in       = (const float*)d_in[8];
    const float* W_noise    = (const float*)d_in[9];
    const float* W_event    = (const float*)d_in[10];

    float* out        = (float*)d_out;
    float* mean_out   = out;               // [B,S]
    float* hidden_out = out + BB * SS;     // [B,S,D]

    pe_kernel<<<(BB * SS * 32 + 255) / 256, 256>>>(event_type, event_time,
                                                   Wt_pos, type_table);
    hidden_kernel<<<dim3(64, BB), 128>>>(event_time, gamma, beta, hidden_out);
    decoder_kernel<<<dim3(SS, BB), 64>>>(noise, W_in, W_noise, W_event,
                                         hidden_out, mean_out);
}

// round 4
// speedup vs baseline: 1.8147x; 1.6865x over previous
#include <cuda_runtime.h>
#include <cstdint>

#define BB 8
#define SS 2048
#define DD 64
#define NSAMP 50

typedef unsigned long long u64;

__device__ float g_pe[BB * SS * DD];   // 4 MB scratch
__device__ float g_emb[BB * SS];       // 64 KB scratch

// ---- packed f32x2 helpers (Blackwell) -------------------------------------
__device__ __forceinline__ u64 pack2(float lo, float hi) {
    u64 r; asm("mov.b64 %0,{%1,%2};" : "=l"(r) : "f"(lo), "f"(hi)); return r;
}
__device__ __forceinline__ void fma2(u64& a, u64 x, u64 y) {
    asm("fma.rn.f32x2 %0,%1,%2,%0;" : "+l"(a) : "l"(x), "l"(y));
}
__device__ __forceinline__ u64 add2(u64 x, u64 y) {
    u64 r; asm("add.rn.f32x2 %0,%1,%2;" : "=l"(r) : "l"(x), "l"(y)); return r;
}
__device__ __forceinline__ float2 unpack2(u64 a) {
    float2 v; asm("mov.b64 {%0,%1},%2;" : "=f"(v.x), "=f"(v.y) : "l"(a)); return v;
}
__device__ __forceinline__ float softplusf(float x) {
    return fmaxf(x, 0.0f) + log1pf(expf(-fabsf(x)));
}
// ---- cp.async helpers ------------------------------------------------------
__device__ __forceinline__ void cp16(void* dst, const void* src) {
    unsigned sa = (unsigned)__cvta_generic_to_shared(dst);
    asm volatile("cp.async.ca.shared.global [%0],[%1],16;" :: "r"(sa), "l"(src));
}
__device__ __forceinline__ void cp4(void* dst, const void* src) {
    unsigned sa = (unsigned)__cvta_generic_to_shared(dst);
    asm volatile("cp.async.ca.shared.global [%0],[%1],4;" :: "r"(sa), "l"(src));
}
__device__ __forceinline__ void cp_commit() {
    asm volatile("cp.async.commit_group;");
}
__device__ __forceinline__ void cp_wait0() {
    asm volatile("cp.async.wait_group 0;");
}

// ---------------------------------------------------------------------------
// Kernel 1: biased positional embedding + type embedding scalar
// ---------------------------------------------------------------------------
__global__ void pe_kernel(const int* __restrict__ etype,
                          const float* __restrict__ etime,
                          const float* __restrict__ Wt_pos,
                          const float* __restrict__ type_table) {
    int idx = blockIdx.x * blockDim.x + threadIdx.x;
    if (idx >= BB * SS * 32) return;
    int k = idx & 31;
    int s = (idx >> 5) & (SS - 1);
    int b = idx >> 16;
    int bs = b * SS + s;
    float t = etime[bs];
    float div = expf((float)(2 * k) * -0.14391156831212787f);
    float a = (float)s * div + t * Wt_pos[k];
    float sv, cv;
    __sincosf(a, &sv, &cv);
    g_pe[bs * DD + k]      = sv;
    g_pe[bs * DD + 32 + k] = cv;
    if (k == 0) {
        int ty = etype[bs];
        g_emb[bs] = (ty == 0) ? 0.0f : type_table[ty] * 8.0f;
    }
}

// ---------------------------------------------------------------------------
// Kernel 2: hidden = causal(scores) @ pe, fused LayerNorm.
// 32-row i-tiles, 512 blocks (heavy-first), 128 threads.
// pe tiles double-buffered via cp.async; 2 syncs per tile.
// ---------------------------------------------------------------------------
__global__ __launch_bounds__(128) void hidden_kernel(
    const float* __restrict__ etime,
    const float* __restrict__ gamma,
    const float* __restrict__ beta,
    float* __restrict__ hidden_out) {
    __shared__ __align__(16) float pe_s[2][32][68];  // padded rows, 17.4 KB
    __shared__ float sc_s[32 * 33];
    __shared__ float ti_s[32], ei_s[32];
    __shared__ float tj_s[2][32], ej_s[2][32];

    const int b   = blockIdx.y;
    const int it  = 63 - blockIdx.x;   // heavy tiles first
    const int tid = threadIdx.x;
    const int dg  = tid & 7;
    const int ig  = tid >> 3;          // 0..15 -> rows 2ig, 2ig+1
    const int si  = tid & 31;
    const int sjg = tid >> 5;

    const float4* gpe4 = (const float4*)g_pe;
    const float*  etb  = etime + b * SS;
    const float*  emb  = g_emb + b * SS;
    const int ntiles = it + 1;

    // prefetch tile 0
    {
#pragma unroll
        for (int r = 0; r < 4; r++) {
            int idx = tid + 128 * r;
            int row = idx >> 4, c = idx & 15;
            cp16(&pe_s[0][row][c * 4], gpe4 + (b * SS + row) * 16 + c);
        }
        if (tid < 32) {
            cp4(&tj_s[0][tid], etb + tid);
            cp4(&ej_s[0][tid], emb + tid);
        }
        cp_commit();
    }
    if (tid < 32) {
        ti_s[tid] = etb[it * 32 + tid];
        ei_s[tid] = emb[it * 32 + tid];
    }
    const float4 gm0 = ((const float4*)gamma)[dg * 2];
    const float4 gm1 = ((const float4*)gamma)[dg * 2 + 1];
    const float4 bt0 = ((const float4*)beta)[dg * 2];
    const float4 bt1 = ((const float4*)beta)[dg * 2 + 1];

    u64 acc2[2][4];
#pragma unroll
    for (int k = 0; k < 2; k++)
#pragma unroll
        for (int m = 0; m < 4; m++) acc2[k][m] = 0ull;

    for (int jt = 0; jt < ntiles; jt++) {
        const int buf = jt & 1;
        cp_wait0();
        __syncthreads();                 // tile jt ready; sc_s/buf^1 consumed

        if (jt + 1 < ntiles) {           // prefetch jt+1
            const int nb = buf ^ 1;
            const int j0 = (jt + 1) * 32;
#pragma unroll
            for (int r = 0; r < 4; r++) {
                int idx = tid + 128 * r;
                int row = idx >> 4, c = idx & 15;
                cp16(&pe_s[nb][row][c * 4],
                     gpe4 + (b * SS + j0 + row) * 16 + c);
            }
            if (tid < 32) {
                cp4(&tj_s[nb][tid], etb + j0 + tid);
                cp4(&ej_s[nb][tid], emb + j0 + tid);
            }
            cp_commit();
        }

        // scores: 32x32, 8 per thread
        {
            const float tii = ti_s[si];
            const float eii = ei_s[si];
            const int iglob = it * 32 + si;
#pragma unroll
            for (int m = 0; m < 8; m++) {
                const int jj = sjg * 8 + m;
                const int jglob = jt * 32 + jj;
                const float td = tii - tj_s[buf][jj];
                const float base = __fdividef(1.0f, 1.0f + 0.5f * td * td);
                const float gate =
                    __fdividef(1.0f, 1.0f + __expf(fabsf(eii - ej_s[buf][jj])));
                sc_s[si * 33 + jj] = (jglob <= iglob) ? base * gate : 0.0f;
            }
        }
        __syncthreads();

#pragma unroll 4
        for (int jj = 0; jj < 32; jj++) {
            const ulonglong2* pr =
                (const ulonglong2*)(&pe_s[buf][jj][dg * 8]);
            const ulonglong2 pa = pr[0];
            const ulonglong2 pb = pr[1];
            const float sv0 = sc_s[(2 * ig) * 33 + jj];
            const float sv1 = sc_s[(2 * ig + 1) * 33 + jj];
            const u64 s0 = pack2(sv0, sv0);
            const u64 s1 = pack2(sv1, sv1);
            fma2(acc2[0][0], s0, pa.x); fma2(acc2[0][1], s0, pa.y);
            fma2(acc2[0][2], s0, pb.x); fma2(acc2[0][3], s0, pb.y);
            fma2(acc2[1][0], s1, pa.x); fma2(acc2[1][1], s1, pa.y);
            fma2(acc2[1][2], s1, pb.x); fma2(acc2[1][3], s1, pb.y);
        }
    }

    // fused LayerNorm (8-lane groups share a row)
#pragma unroll
    for (int k = 0; k < 2; k++) {
        float f[8];
#pragma unroll
        for (int m = 0; m < 4; m++) {
            float2 v = unpack2(acc2[k][m]);
            f[2 * m] = v.x; f[2 * m + 1] = v.y;
        }
        float sum = 0.0f, sq = 0.0f;
#pragma unroll
        for (int m = 0; m < 8; m++) { sum += f[m]; sq += f[m] * f[m]; }
#pragma unroll
        for (int o = 1; o < 8; o <<= 1) {
            sum += __shfl_xor_sync(0xffffffffu, sum, o);
            sq  += __shfl_xor_sync(0xffffffffu, sq,  o);
        }
        const float mu  = sum * (1.0f / 64.0f);
        const float var = sq * (1.0f / 64.0f) - mu * mu;
        const float inv = rsqrtf(var + 1e-6f);
        const int row = it * 32 + 2 * ig + k;
        float* outp = hidden_out + ((size_t)(b * SS + row)) * 64 + dg * 8;
        float4 o0, o1;
        o0.x = (f[0] - mu) * inv * gm0.x + bt0.x;
        o0.y = (f[1] - mu) * inv * gm0.y + bt0.y;
        o0.z = (f[2] - mu) * inv * gm0.z + bt0.z;
        o0.w = (f[3] - mu) * inv * gm0.w + bt0.w;
        o1.x = (f[4] - mu) * inv * gm1.x + bt1.x;
        o1.y = (f[5] - mu) * inv * gm1.y + bt1.y;
        o1.z = (f[6] - mu) * inv * gm1.z + bt1.z;
        o1.w = (f[7] - mu) * inv * gm1.w + bt1.w;
        ((float4*)outp)[0] = o0;
        ((float4*)outp)[1] = o1;
    }
}

// ---------------------------------------------------------------------------
// Kernel 3: GAN decoder. Block = 128 threads, 4 consecutive (b,s) steps.
// Noise double-buffered via cp.async (bulk coalesced); W_noise row in regs;
// W_in resident in smem (amortized over 4 steps); per-sample e-reduction by
// warp shuffles -> gpart[50][2]; no per-sample barriers.
// ---------------------------------------------------------------------------
__global__ __launch_bounds__(128, 4) void decoder_kernel(
    const float* __restrict__ noise,
    const float* __restrict__ W_in,
    const float* __restrict__ W_noise,
    const float* __restrict__ W_event,
    const float* __restrict__ hidden,
    float* __restrict__ mean_out) {
    __shared__ __align__(16) float win_s[64][68];     // 17.4 KB
    __shared__ __align__(16) float4 nbuf[2][800];     // 25.6 KB
    __shared__ float h_s[2][64];
    __shared__ float gpart[NSAMP][2];
    __shared__ float pred[2];

    const int s0 = blockIdx.x * 4, b = blockIdx.y;
    const int bs0 = b * SS + s0;
    const int tid   = threadIdx.x;
    const int lane  = tid & 31;
    const int e     = tid & 63;
    const int ngrp  = tid >> 6;          // 0 or 1: samples n = ngrp + 2k
    const int whalf = (tid >> 5) & 1;    // e-low / e-high warp
    const int warp  = tid >> 5;

    // --- prologue: stage W_noise (into nbuf[0]) and W_in ---
    {
        const float4* wn4 = (const float4*)W_noise;
        const float4* wi4 = (const float4*)W_in;
#pragma unroll
        for (int r = 0; r < 8; r++) {
            int idx = tid + 128 * r;      // 0..1023
            cp16(&nbuf[0][idx], wn4 + idx);
            int row = idx >> 4, c = idx & 15;
            cp16(&win_s[row][c * 4], wi4 + idx);
        }
        cp_commit();
        cp_wait0();
    }
    __syncthreads();

    u64 wr[32];
    {
        const ulonglong2* q = (const ulonglong2*)&nbuf[0][e * 16];
#pragma unroll
        for (int i = 0; i < 16; i++) {
            const ulonglong2 v = q[i];
            wr[2 * i] = v.x; wr[2 * i + 1] = v.y;
        }
    }
    const float wev = W_event[e];
    __syncthreads();                      // all wr reads done before overwrite

    // prefetch noise + hidden for step 0 into buffer 0
    {
        const float4* src = (const float4*)(noise + (size_t)bs0 * NSAMP * 64);
#pragma unroll
        for (int r = 0; r < 7; r++) {
            int idx = tid + 128 * r;
            if (idx < 800) cp16(&nbuf[0][idx], src + idx);
        }
        if (tid < 64) cp4(&h_s[0][tid], hidden + (size_t)bs0 * 64 + tid);
        cp_commit();
    }

    for (int v = 0; v < 4; v++) {
        const int buf = v & 1;
        const int bs = bs0 + v;
        cp_wait0();
        __syncthreads();                  // step v data ready; gpart consumed

        if (v < 3) {                      // prefetch step v+1
            const float4* src =
                (const float4*)(noise + (size_t)(bs + 1) * NSAMP * 64);
            const int nb = buf ^ 1;
#pragma unroll
            for (int r = 0; r < 7; r++) {
                int idx = tid + 128 * r;
                if (idx < 800) cp16(&nbuf[nb][idx], src + idx);
            }
            if (tid < 64) cp4(&h_s[nb][tid], hidden + (size_t)(bs + 1) * 64 + tid);
            cp_commit();
        }

        // proj[e] = W_in[e,:] . hidden[bs]
        float pj = 0.0f;
#pragma unroll
        for (int i = 0; i < 16; i++) {
            const float4 w = *(const float4*)&win_s[e][i * 4];
            pj += w.x * h_s[buf][4 * i]     + w.y * h_s[buf][4 * i + 1]
                + w.z * h_s[buf][4 * i + 2] + w.w * h_s[buf][4 * i + 3];
        }

        // 25 samples per thread; e-reduction by warp shuffle
        for (int k = 0; k < 25; k++) {
            const int n = ngrp + 2 * k;
            const ulonglong2* row = (const ulonglong2*)&nbuf[buf][n * 16];
            u64 acc[8];
#pragma unroll
            for (int m = 0; m < 8; m++) acc[m] = 0ull;
#pragma unroll
            for (int i = 0; i < 16; i++) {
                const ulonglong2 nv = row[i];
                fma2(acc[(2 * i) & 7],     nv.x, wr[2 * i]);
                fma2(acc[(2 * i + 1) & 7], nv.y, wr[2 * i + 1]);
            }
            u64 a0 = add2(add2(acc[0], acc[4]), add2(acc[2], acc[6]));
            u64 a1 = add2(add2(acc[1], acc[5]), add2(acc[3], acc[7]));
            float2 vv = unpack2(add2(a0, a1));
            float g = fmaxf(pj + vv.x + vv.y, 0.0f) * wev;
#pragma unroll
            for (int o = 16; o > 0; o >>= 1)
                g += __shfl_xor_sync(0xffffffffu, g, o);
            if (lane == 0) gpart[n][whalf] = g;
        }
        __syncthreads();                  // gpart complete

        // reduce 50 samples (warps 0,1)
        if (tid < 64) {
            float t = 0.0f;
            if (tid < NSAMP) t = softplusf(gpart[tid][0] + gpart[tid][1]);
#pragma unroll
            for (int o = 16; o > 0; o >>= 1)
                t += __shfl_xor_sync(0xffffffffu, t, o);
            if (lane == 0) pred[warp] = t;
        }
        __syncthreads();
        if (tid == 0) mean_out[bs] = (pred[0] + pred[1]) * (1.0f / NSAMP);
    }
}

// ---------------------------------------------------------------------------
extern "C" void kernel_launch(void* const* d_in, const int* in_sizes, int n_in,
                              void* d_out, int out_size) {
    const int*   event_type = (const int*)d_in[0];
    const float* event_time = (const float*)d_in[1];
    const float* noise      = (const float*)d_in[3];
    const float* Wt_pos     = (const float*)d_in[4];
    const float* type_table = (const float*)d_in[5];
    const float* gamma      = (const float*)d_in[6];
    const float* beta       = (const float*)d_in[7];
    const float* W_in       = (const float*)d_in[8];
    const float* W_noise    = (const float*)d_in[9];
    const float* W_event    = (const float*)d_in[10];

    float* out        = (float*)d_out;
    float* mean_out   = out;               // [B,S]
    float* hidden_out = out + BB * SS;     // [B,S,D]

    pe_kernel<<<(BB * SS * 32 + 255) / 256, 256>>>(event_type, event_time,
                                                   Wt_pos, type_table);
    hidden_kernel<<<dim3(64, BB), 128>>>(event_time, gamma, beta, hidden_out);
    decoder_kernel<<<dim3(SS / 4, BB), 128>>>(noise, W_in, W_noise, W_event,
                                              hidden_out, mean_out);
}